// round 15
// baseline (speedup 1.0000x reference)
#include <cuda_runtime.h>
#include <cuda_fp16.h>
#include <cstdint>

#define P       4096
#define MOUT    64
#define ITILE   64               // i-rows per CTA
#define SPLITS  4
#define KSPLIT  (P / SPLITS)     // 1024
#define KC      128
#define NCHUNK  (KSPLIT / KC)    // 8
#define NT      256
#define EXP_NEG 0.36787907f      // expf(-1.000001f)

// ---------------- device scratch ----------------
__device__ __half g_Bh[P * MOUT];                  // [k][m] fp16 — SAME layout as hidden
__device__ float  g_Dpart[SPLITS][P][MOUT];        // split-K partials (4 MB)
__device__ int    g_cnt[SPLITS][P];
__device__ int    g_total;                         // sticky atomicOr(1); replay-safe

// ---------------- helpers ----------------
__device__ __forceinline__ uint32_t smem_u32(const void* p) {
    uint32_t a;
    asm("{ .reg .u64 t; cvta.to.shared.u64 t, %1; cvt.u32.u64 %0, t; }" : "=r"(a) : "l"(p));
    return a;
}
// A tiles: 256B rows (128 fp16), 16x16B chunks, chunk' = chunk ^ (row&7)  [validated R6-R14]
__device__ __forceinline__ uint32_t sw2(int row, int kbyte) {
    return (uint32_t)(row * 256) + (uint32_t)((((kbyte >> 4) ^ (row & 7)) << 4) | (kbyte & 15));
}
// B tiles: 128B rows (64 fp16 = one k-row), 8x16B chunks, same XOR  [validated R9-R11]
__device__ __forceinline__ uint32_t swb(int row, int kbyte) {
    return (uint32_t)(row * 128) + (uint32_t)((((kbyte >> 4) ^ (row & 7)) << 4) | (kbyte & 15));
}
__device__ __forceinline__ void sts64(uint32_t addr, uint32_t x, uint32_t y) {
    asm volatile("st.shared.v2.b32 [%0], {%1, %2};" :: "r"(addr), "r"(x), "r"(y) : "memory");
}
__device__ __forceinline__ void cp16(uint32_t dst, const void* src) {
    asm volatile("cp.async.cg.shared.global [%0], [%1], 16;" :: "r"(dst), "l"(src) : "memory");
}
#define CP_COMMIT() asm volatile("cp.async.commit_group;" ::: "memory")
#define CP_WAIT0()  asm volatile("cp.async.wait_group 0;" ::: "memory")
__device__ __forceinline__ void ldsm4(uint32_t* r, uint32_t addr) {
    asm volatile("ldmatrix.sync.aligned.m8n8.x4.shared.b16 {%0,%1,%2,%3}, [%4];"
                 : "=r"(r[0]), "=r"(r[1]), "=r"(r[2]), "=r"(r[3]) : "r"(addr));
}
__device__ __forceinline__ void ldsm4t(uint32_t* r, uint32_t addr) {
    asm volatile("ldmatrix.sync.aligned.m8n8.x4.trans.shared.b16 {%0,%1,%2,%3}, [%4];"
                 : "=r"(r[0]), "=r"(r[1]), "=r"(r[2]), "=r"(r[3]) : "r"(addr));
}
__device__ __forceinline__ void mma16816(float* c, const uint32_t* a, const uint32_t* b) {
    asm volatile("mma.sync.aligned.m16n8k16.row.col.f32.f16.f16.f32 "
                 "{%0,%1,%2,%3}, {%4,%5,%6,%7}, {%8,%9}, {%0,%1,%2,%3};"
                 : "+f"(c[0]), "+f"(c[1]), "+f"(c[2]), "+f"(c[3])
                 : "r"(a[0]), "r"(a[1]), "r"(a[2]), "r"(a[3]), "r"(b[0]), "r"(b[1]));
}

// ---------------- kernel 1: straight fp32 -> fp16 conversion (no transpose) ----------------
__global__ void prep_kernel(const float* __restrict__ hidden) {
    // thread handles 8 consecutive floats: 2 independent float4 loads -> 1 uint4 store
    size_t base = ((size_t)blockIdx.x * NT + threadIdx.x) * 8;   // 128 CTAs cover P*MOUT
    float4 v0 = *reinterpret_cast<const float4*>(hidden + base);
    float4 v1 = *reinterpret_cast<const float4*>(hidden + base + 4);
    __half2 a = __floats2half2_rn(v0.x, v0.y);
    __half2 b = __floats2half2_rn(v0.z, v0.w);
    __half2 c = __floats2half2_rn(v1.x, v1.y);
    __half2 d = __floats2half2_rn(v1.z, v1.w);
    uint4 pk;
    pk.x = *reinterpret_cast<uint32_t*>(&a);
    pk.y = *reinterpret_cast<uint32_t*>(&b);
    pk.z = *reinterpret_cast<uint32_t*>(&c);
    pk.w = *reinterpret_cast<uint32_t*>(&d);
    *reinterpret_cast<uint4*>(g_Bh + base) = pk;
}

// ---------------- kernel 2: fp16 mma GEMM (R14 structure; B via ldsm.trans) ----------------
extern __shared__ __align__(16) char smem[];   // [A0 16K][A1 16K][B0 16K][B1 16K]

__global__ __launch_bounds__(NT)
void gemm_kernel(const int* __restrict__ nei) {
    const int tid    = threadIdx.x;
    const int lane   = tid & 31;
    const int w      = tid >> 5;
    const int warp_m = w & 3;        // i-offset = warp_m*16
    const int warp_n = w >> 2;       // n-offset = warp_n*32
    const int split  = blockIdx.x;
    const int i0     = blockIdx.y * ITILE;
    const int k0base = split * KSPLIT;

    const uint32_t sbase = smem_u32(smem);
    const uint32_t sA[2] = {sbase,         sbase + 16384};
    const uint32_t sB[2] = {sbase + 32768, sbase + 49152};
    const int kl = lane * 4;

    float acc[4][4];
    #pragma unroll
    for (int b = 0; b < 4; ++b)
        #pragma unroll
        for (int c = 0; c < 4; ++c) acc[b][c] = 0.0f;
    int cnt[8];
    #pragma unroll
    for (int s = 0; s < 8; ++s) cnt[s] = 0;

    int4 va[8];

    auto fill_B = [&](int c, int b) {   // [k][m] tile: 128 k-rows x 128B, cp.async swizzled
        const int k0 = k0base + c * KC;
        #pragma unroll
        for (int q = 0; q < 4; ++q) {
            int idx = q * NT + tid;
            int kr = idx >> 3, ch = idx & 7;
            cp16(sB[b] + (uint32_t)(kr * 128) + (uint32_t)(((ch ^ (kr & 7)) << 4)),
                 g_Bh + (size_t)(k0 + kr) * MOUT + ch * 8);
        }
    };
    auto load_A = [&](int c) {
        const int k0 = k0base + c * KC;
        #pragma unroll
        for (int s = 0; s < 8; ++s) {
            int row = w + 8 * s;
            va[s] = *reinterpret_cast<const int4*>(nei + (size_t)(i0 + row) * P + k0 + kl);
        }
    };
    auto sts_A = [&](int b) {
        #pragma unroll
        for (int s = 0; s < 8; ++s) {
            int row = w + 8 * s;
            // nei values are {0,1}: fp16(v) = v * 0x3C00 — pure IMAD path (validated R14)
            uint32_t lo = (uint32_t)va[s].x * 0x3C00u + (uint32_t)va[s].y * 0x3C000000u;
            uint32_t hi = (uint32_t)va[s].z * 0x3C00u + (uint32_t)va[s].w * 0x3C000000u;
            cnt[s] += va[s].x + va[s].y + va[s].z + va[s].w;
            sts64(sA[b] + sw2(row, kl * 2), lo, hi);
        }
    };

    fill_B(0, 0); CP_COMMIT();
    load_A(0);
    sts_A(0);
    CP_WAIT0();
    __syncthreads();

    #pragma unroll 1
    for (int c = 0; c < NCHUNK; ++c) {
        const int b  = c & 1;
        const int nb = b ^ 1;
        if (c + 1 < NCHUNK) { fill_B(c + 1, nb); CP_COMMIT(); load_A(c + 1); }

        #pragma unroll
        for (int k16 = 0; k16 < KC / 16; ++k16) {
            uint32_t afr[4];
            {
                int row = warp_m * 16 + (lane & 15);
                int kb  = k16 * 32 + ((lane >> 4) << 4);
                ldsm4(afr, sA[b] + sw2(row, kb));
            }
            uint32_t bfr[2][4];
            #pragma unroll
            for (int g = 0; g < 2; ++g) {          // trans-load from [k][m] (validated R9-R11)
                int krow = k16 * 16 + (lane & 15);
                int mb   = warp_n * 32 + g * 16 + ((lane >> 4) << 3);
                ldsm4t(bfr[g], sB[b] + swb(krow, mb * 2));
            }
            #pragma unroll
            for (int g = 0; g < 2; ++g) {
                mma16816(acc[2 * g],     afr, &bfr[g][0]);   // n cols +0..7
                mma16816(acc[2 * g + 1], afr, &bfr[g][2]);   // n cols +8..15
            }
        }

        if (c + 1 < NCHUNK) sts_A(nb);
        CP_WAIT0();
        __syncthreads();
    }

    // counts: warp-wide reduce per owned row, plain stores (exclusive ownership)
    int any = 0;
    #pragma unroll
    for (int s = 0; s < 8; ++s) {
        int v = __reduce_add_sync(0xffffffffu, cnt[s]);
        if (lane == 0) g_cnt[split][i0 + w + 8 * s] = v;
        any |= v;
    }
    if (lane == 0 && any) atomicOr(&g_total, 1);   // idempotent -> replay-safe

    // epilogue: c-frag (row, 2 adjacent cols) -> float2 stores
    {
        int ibase = i0 + warp_m * 16 + (lane >> 2);
        #pragma unroll
        for (int g = 0; g < 2; ++g) {
            #pragma unroll
            for (int t = 0; t < 2; ++t) {
                int n0 = warp_n * 32 + g * 16 + t * 8 + 2 * (lane & 3);
                const float* cfr = acc[2 * g + t];
                *reinterpret_cast<float2*>(&g_Dpart[split][ibase][n0]) =
                    make_float2(cfr[0], cfr[1]);
                *reinterpret_cast<float2*>(&g_Dpart[split][ibase + 8][n0]) =
                    make_float2(cfr[2], cfr[3]);
            }
        }
    }
}

// ---------------- kernel 3: combine splits + analytic softmax scale ----------------
__global__ void finalize_kernel(const float* __restrict__ hidden,
                                float* __restrict__ out) {
    int idx4 = (blockIdx.x * NT + threadIdx.x) * 4;    // 256 CTAs
    if (idx4 >= P * MOUT) return;
    int i = idx4 >> 6;

    if (g_total > 0) {
        float4 a[SPLITS];
        #pragma unroll
        for (int sp = 0; sp < SPLITS; ++sp)
            a[sp] = *reinterpret_cast<const float4*>(&g_Dpart[sp][0][0] + idx4);
        int c0 = g_cnt[0][i], c1 = g_cnt[1][i], c2 = g_cnt[2][i], c3 = g_cnt[3][i];

        float cnt = (float)(c0 + c1 + c2 + c3);
        float inv = 1.0f / (cnt + ((float)P - cnt) * EXP_NEG);

        float4 s0 = a[0];
        #pragma unroll
        for (int sp = 1; sp < SPLITS; ++sp) {
            s0.x += a[sp].x; s0.y += a[sp].y; s0.z += a[sp].z; s0.w += a[sp].w;
        }
        s0.x *= inv; s0.y *= inv; s0.z *= inv; s0.w *= inv;
        *reinterpret_cast<float4*>(out + idx4) = s0;
    } else {
        *reinterpret_cast<float4*>(out + idx4) =
            *reinterpret_cast<const float4*>(hidden + idx4);
    }
}

// ---------------- launch ----------------
extern "C" void kernel_launch(void* const* d_in, const int* in_sizes, int n_in,
                              void* d_out, int out_size) {
    const float* hidden = (const float*)d_in[0];
    // d_in[1] (corr_index) is unused by the reference math — never read.
    const int*   nei    = (const int*)d_in[2];
    float*       out    = (float*)d_out;

    const int smem_bytes = 65536;   // 2 x (16K A + 16K B)
    cudaFuncSetAttribute(gemm_kernel,
                         cudaFuncAttributeMaxDynamicSharedMemorySize, smem_bytes);

    prep_kernel<<<P * MOUT / (8 * NT), NT>>>(hidden);                 // 128 CTAs
    gemm_kernel<<<dim3(SPLITS, P / ITILE), NT, smem_bytes>>>(nei);    // 256 CTAs
    finalize_kernel<<<P * MOUT / (4 * NT), NT>>>(hidden, out);        // 256 CTAs
}